// round 9
// baseline (speedup 1.0000x reference)
#include <cuda_runtime.h>

#define CCH 128
#define OCH 128
#define HH  56
#define WW  56
#define BB  32

#define NTHR 224   // 7 warps: og = tid&31 (4 o each -> 2 f32x2 pairs), wg = tid>>5 (8 w each)

// scratch: intermediate activations + quantized (transposed) weights
__device__ float g_t[(size_t)BB * CCH * HH * WW];     // ~51.4 MB
__device__ float g_w1[9 * CCH * OCH];                  // [i][c][o]
__device__ float g_w2[9 * CCH * OCH];

typedef unsigned long long u64t;

// Effective LSQ alpha, matching jax grad_scale forward rounding exactly
__device__ __forceinline__ float lsq_alpha_eff(float a, double g) {
    float s32 = (float)g;
    float om  = (float)(1.0 - g);
    return __fadd_rn(__fmul_rn(a, s32), __fmul_rn(a, om));
}

__device__ __forceinline__ u64t dup2(float x) {
    u64t r;
    asm("mov.b64 %0, {%1, %1};" : "=l"(r) : "f"(x));
    return r;
}
__device__ __forceinline__ u64t ffma2(u64t a, u64t b, u64t c) {
    u64t d;
    asm("fma.rn.f32x2 %0, %1, %2, %3;" : "=l"(d) : "l"(a), "l"(b), "l"(c));
    return d;
}
__device__ __forceinline__ void unpack2(u64t v, float& lo, float& hi) {
    asm("mov.b64 {%0, %1}, %2;" : "=f"(lo), "=f"(hi) : "l"(v));
}

// wq_t[i][c][o] = round(clip(W[i][o][c]/a_eff, -4, 3)) * a_eff
__global__ void quant_w_kernel(const float* __restrict__ W,
                               const float* __restrict__ a_w,
                               float* __restrict__ wt) {
    int idx = blockIdx.x * blockDim.x + threadIdx.x;
    if (idx >= 9 * CCH * OCH) return;
    int o = idx % OCH;
    int c = (idx / OCH) % CCH;
    int i = idx / (OCH * CCH);
    const double gw = 1.0 / sqrt((double)(OCH * CCH * 3));   // 1/sqrt(49152)
    float a = lsq_alpha_eff(a_w[i], gw);
    float v = __fdiv_rn(W[((size_t)i * OCH + o) * CCH + c], a);
    v = fminf(fmaxf(v, -4.f), 3.f);
    wt[idx] = __fmul_rn(rintf(v), a);
}

// One block = one (b, h) output row: out[b][0..127][h][0..55]
// smem: xs2 [128 c][58 w] duplicated f32 pairs (8B) = 59392 B, then
//       ws  [3 dw][32 cc][128 o] f32 = 49152 B.  Total 108544 B.
__global__ __launch_bounds__(NTHR, 1)
void conv_kernel(const float* __restrict__ xin,       // [B][C][H][W]
                 const float* __restrict__ wqt,       // [9][C][O], i = dw*3+dh
                 const float* __restrict__ ap_ptr,    // scalar alpha_p
                 const float* __restrict__ gamma, const float* __restrict__ beta,
                 const float* __restrict__ mean,  const float* __restrict__ var,
                 const float* __restrict__ resid,
                 float* __restrict__ out,
                 int add_res) {
    extern __shared__ char smem_raw[];
    u64t*  xs2 = (u64t*)smem_raw;                       // [128][58] dup pairs
    float* ws  = (float*)(smem_raw + CCH * 58 * 8);     // [3][32][128]

    const int h   = blockIdx.x;
    const int b   = blockIdx.y;
    const int tid = threadIdx.x;
    const int og  = tid & 31;
    const int wg  = tid >> 5;            // 0..6
    const int o0  = og * 4;
    const int wb  = wg * 8;

    const double gp = 1.0 / sqrt((double)BB * OCH * HH * WW * 3.0);
    const float ap = lsq_alpha_eff(ap_ptr[0], gp);

    float out_acc[4][8];
    #pragma unroll
    for (int oi = 0; oi < 4; ++oi)
        #pragma unroll
        for (int wi = 0; wi < 8; ++wi) out_acc[oi][wi] = 0.f;

    for (int r = 0; r < 3; ++r) {           // input row h+r-1
        // stage one padded input row as duplicated pairs
        {
            const int hs = h + r - 1;
            const bool hok = (unsigned)hs < HH;
            const float* xrow = xin + (((size_t)b * CCH) * HH + hs) * WW;
            __syncthreads();                // prev iter consumers done (xs2/ws reuse)
            for (int idx = tid; idx < CCH * 58; idx += NTHR) {
                int wi = idx % 58;
                int c  = idx / 58;
                int w  = wi - 1;
                float v = 0.f;
                if (hok && (unsigned)w < WW)
                    v = xrow[(size_t)c * (HH * WW) + w];
                xs2[idx] = dup2(v);
            }
        }

        u64t facc[3][2][8];                 // [dw][o-pair][w]
        #pragma unroll
        for (int dw = 0; dw < 3; ++dw)
            #pragma unroll
            for (int op = 0; op < 2; ++op)
                #pragma unroll
                for (int wi = 0; wi < 8; ++wi) facc[dw][op][wi] = 0ull;

        for (int ch = 0; ch < 4; ++ch) {    // 32-channel chunks
            // stage weights [3 dw][32 cc][128 o] for this (r, chunk)
            if (ch) __syncthreads();        // prev chunk consumed
            for (int idx = tid; idx < 3 * 32 * OCH; idx += NTHR) {
                int o  = idx & (OCH - 1);
                int t2 = idx >> 7;          // dw*32 + cc
                int cc = t2 & 31;
                int dw = t2 >> 5;
                ws[idx] = wqt[((size_t)(dw * 3 + r) * CCH + (ch * 32 + cc)) * OCH + o];
            }
            __syncthreads();                // xs2 + ws ready

            const u64t* xbase = xs2 + (size_t)(ch * 32) * 58 + wb;
            #pragma unroll 2
            for (int cc = 0; cc < 32; ++cc) {
                u64t xv[10];
                #pragma unroll
                for (int j = 0; j < 10; ++j) xv[j] = xbase[cc * 58 + j];
                const float* wrow = ws + cc * OCH + o0;
                #pragma unroll
                for (int dw = 0; dw < 3; ++dw) {
                    ulonglong2 wp = *(const ulonglong2*)(wrow + dw * 32 * OCH);
                    #pragma unroll
                    for (int wi = 0; wi < 8; ++wi) {
                        facc[dw][0][wi] = ffma2(wp.x, xv[wi + dw], facc[dw][0][wi]);
                        facc[dw][1][wi] = ffma2(wp.y, xv[wi + dw], facc[dw][1][wi]);
                    }
                }
            }
        }

        // per-shift LSQ psum quantization, then accumulate (exact multiples of ap)
        #pragma unroll
        for (int dw = 0; dw < 3; ++dw)
            #pragma unroll
            for (int op = 0; op < 2; ++op)
                #pragma unroll
                for (int wi = 0; wi < 8; ++wi) {
                    float lo, hi;
                    unpack2(facc[dw][op][wi], lo, hi);
                    float ql = fminf(fmaxf(__fdiv_rn(lo, ap), -4.f), 3.f);
                    float qh = fminf(fmaxf(__fdiv_rn(hi, ap), -4.f), 3.f);
                    out_acc[2 * op][wi]     = __fadd_rn(out_acc[2 * op][wi],     __fmul_rn(rintf(ql), ap));
                    out_acc[2 * op + 1][wi] = __fadd_rn(out_acc[2 * op + 1][wi], __fmul_rn(rintf(qh), ap));
                }
    }

    // epilogue: BN (+residual) + ReLU with jax-matching rounding (NO fma contraction)
    const size_t obase0 = ((size_t)b * OCH) * (HH * WW) + (size_t)h * WW + wb;
    #pragma unroll
    for (int oi = 0; oi < 4; ++oi) {
        int o = o0 + oi;
        float invs = __fdiv_rn(gamma[o], sqrtf(__fadd_rn(var[o], 1e-5f)));
        float sh   = __fadd_rn(beta[o], -__fmul_rn(mean[o], invs));
        size_t base = obase0 + (size_t)o * (HH * WW);
        float vals[8];
        #pragma unroll
        for (int wi = 0; wi < 8; ++wi)
            vals[wi] = __fadd_rn(__fmul_rn(out_acc[oi][wi], invs), sh);
        if (add_res) {
            float4 r0 = *(const float4*)(resid + base);
            float4 r1 = *(const float4*)(resid + base + 4);
            vals[0] = __fadd_rn(vals[0], r0.x); vals[1] = __fadd_rn(vals[1], r0.y);
            vals[2] = __fadd_rn(vals[2], r0.z); vals[3] = __fadd_rn(vals[3], r0.w);
            vals[4] = __fadd_rn(vals[4], r1.x); vals[5] = __fadd_rn(vals[5], r1.y);
            vals[6] = __fadd_rn(vals[6], r1.z); vals[7] = __fadd_rn(vals[7], r1.w);
        }
        float4 s0 = make_float4(fmaxf(vals[0], 0.f), fmaxf(vals[1], 0.f),
                                fmaxf(vals[2], 0.f), fmaxf(vals[3], 0.f));
        float4 s1 = make_float4(fmaxf(vals[4], 0.f), fmaxf(vals[5], 0.f),
                                fmaxf(vals[6], 0.f), fmaxf(vals[7], 0.f));
        *(float4*)(out + base)     = s0;
        *(float4*)(out + base + 4) = s1;
    }
}

extern "C" void kernel_launch(void* const* d_in, const int* in_sizes, int n_in,
                              void* d_out, int out_size) {
    const float* x    = (const float*)d_in[0];
    const float* W1   = (const float*)d_in[1];
    const float* a_w1 = (const float*)d_in[2];
    const float* W2   = (const float*)d_in[3];
    const float* a_w2 = (const float*)d_in[4];
    const float* a_p1 = (const float*)d_in[5];
    const float* a_p2 = (const float*)d_in[6];
    const float* g1   = (const float*)d_in[7];
    const float* b1   = (const float*)d_in[8];
    const float* m1   = (const float*)d_in[9];
    const float* v1   = (const float*)d_in[10];
    const float* g2   = (const float*)d_in[11];
    const float* b2   = (const float*)d_in[12];
    const float* m2   = (const float*)d_in[13];
    const float* v2   = (const float*)d_in[14];
    float* out = (float*)d_out;

    float *t, *w1q, *w2q;
    cudaGetSymbolAddress((void**)&t,   g_t);
    cudaGetSymbolAddress((void**)&w1q, g_w1);
    cudaGetSymbolAddress((void**)&w2q, g_w2);

    const int smem_bytes = CCH * 58 * 8 + 3 * 32 * OCH * 4;  // 59392 + 49152 = 108544
    cudaFuncSetAttribute(conv_kernel, cudaFuncAttributeMaxDynamicSharedMemorySize, smem_bytes);

    const int nw = 9 * CCH * OCH;
    quant_w_kernel<<<(nw + 255) / 256, 256>>>(W1, a_w1, w1q);
    quant_w_kernel<<<(nw + 255) / 256, 256>>>(W2, a_w2, w2q);

    dim3 grid(HH, BB);
    conv_kernel<<<grid, NTHR, smem_bytes>>>(x, w1q, a_p1, g1, b1, m1, v1, nullptr, t, 0);
    conv_kernel<<<grid, NTHR, smem_bytes>>>(t, w2q, a_p2, g2, b2, m2, v2, x, out, 1);
}

// round 10
// speedup vs baseline: 2.0124x; 2.0124x over previous
#include <cuda_runtime.h>

#define CCH 128
#define OCH 128
#define HH  56
#define WW  56
#define BB  32

#define NTHR 448   // 14 warps: og = tid&31 (4 o each), wg = tid>>5 (0..13, 4 w each)

// scratch: intermediate activations + quantized (transposed) weights
__device__ float g_t[(size_t)BB * CCH * HH * WW];     // ~51.4 MB
__device__ float g_w1[9 * CCH * OCH];                  // [i][c][o]
__device__ float g_w2[9 * CCH * OCH];

// Effective LSQ alpha, matching jax grad_scale forward rounding exactly:
//   a_eff = fl(a*g32) + fl(a*fl32(1-g)), g computed in double
__device__ __forceinline__ float lsq_alpha_eff(float a, double g) {
    float s32 = (float)g;
    float om  = (float)(1.0 - g);
    return __fadd_rn(__fmul_rn(a, s32), __fmul_rn(a, om));
}

// wq_t[i][c][o] = round(clip(W[i][o][c]/a_eff, -4, 3)) * a_eff
__global__ void quant_w_kernel(const float* __restrict__ W,
                               const float* __restrict__ a_w,
                               float* __restrict__ wt) {
    int idx = blockIdx.x * blockDim.x + threadIdx.x;
    if (idx >= 9 * CCH * OCH) return;
    int o = idx % OCH;
    int c = (idx / OCH) % CCH;
    int i = idx / (OCH * CCH);
    const double gw = 1.0 / sqrt((double)(OCH * CCH * 3));   // 1/sqrt(49152)
    float a = lsq_alpha_eff(a_w[i], gw);
    float v = __fdiv_rn(W[((size_t)i * OCH + o) * CCH + c], a);
    v = fminf(fmaxf(v, -4.f), 3.f);
    wt[idx] = __fmul_rn(rintf(v), a);
}

// One block = one (b, h) output row: out[b][0..127][h][0..55]
__global__ __launch_bounds__(NTHR, 1)
void conv_kernel(const float* __restrict__ xin,       // [B][C][H][W]
                 const float* __restrict__ wqt,       // [9][C][O], i = dw*3+dh
                 const float* __restrict__ ap_ptr,    // scalar alpha_p
                 const float* __restrict__ gamma, const float* __restrict__ beta,
                 const float* __restrict__ mean,  const float* __restrict__ var,
                 const float* __restrict__ resid,
                 float* __restrict__ out,
                 int add_res) {
    extern __shared__ float smem[];
    float* xs = smem;                    // [3][128][58], col offset +1 (pad)
    float* ws = smem + 3 * CCH * 58;     // [3 dw][32 cc][128 o]

    const int h   = blockIdx.x;
    const int b   = blockIdx.y;
    const int tid = threadIdx.x;
    const int og  = tid & 31;
    const int wg  = tid >> 5;            // 0..13
    const int o0  = og * 4;
    const int w0  = wg * 4;

    // stage 3 padded input rows
    for (int idx = tid; idx < 3 * CCH * 58; idx += NTHR) {
        int wi = idx % 58;
        int rc = idx / 58;
        int c  = rc % CCH;
        int r  = rc / CCH;
        int hs = h + r - 1;
        int w  = wi - 1;
        float v = 0.f;
        if ((unsigned)hs < HH && (unsigned)w < WW)
            v = xin[(((size_t)b * CCH + c) * HH + hs) * WW + w];
        xs[idx] = v;
    }

    const double gp = 1.0 / sqrt((double)BB * OCH * HH * WW * 3.0);
    const float ap = lsq_alpha_eff(ap_ptr[0], gp);

    float out_acc[4][4];
    #pragma unroll
    for (int oi = 0; oi < 4; ++oi)
        #pragma unroll
        for (int wi = 0; wi < 4; ++wi) out_acc[oi][wi] = 0.f;

    for (int r = 0; r < 3; ++r) {           // r = dh (input row h+r-1)
        float facc[3][4][4];
        #pragma unroll
        for (int dw = 0; dw < 3; ++dw)
            #pragma unroll
            for (int oi = 0; oi < 4; ++oi)
                #pragma unroll
                for (int wi = 0; wi < 4; ++wi) facc[dw][oi][wi] = 0.f;

        for (int ch = 0; ch < 4; ++ch) {    // 32-channel chunks
            __syncthreads();                // xs ready / prev ws consumed
            for (int idx = tid; idx < 3 * 32 * OCH; idx += NTHR) {
                int o  = idx & (OCH - 1);
                int t2 = idx >> 7;          // dw*32 + cc
                int cc = t2 & 31;
                int dw = t2 >> 5;
                ws[idx] = wqt[((size_t)(dw * 3 + r) * CCH + (ch * 32 + cc)) * OCH + o];
            }
            __syncthreads();

            const float* xbase = xs + (r * CCH + ch * 32) * 58 + w0;
            #pragma unroll 4
            for (int cc = 0; cc < 32; ++cc) {
                float xv[6];
                #pragma unroll
                for (int j = 0; j < 6; ++j) xv[j] = xbase[cc * 58 + j];
                #pragma unroll
                for (int dw = 0; dw < 3; ++dw) {
                    float4 w4 = *(const float4*)(ws + (dw * 32 + cc) * OCH + o0);
                    float wa0 = w4.x, wa1 = w4.y, wa2 = w4.z, wa3 = w4.w;
                    #pragma unroll
                    for (int wi = 0; wi < 4; ++wi) {
                        float xvv = xv[wi + dw];
                        facc[dw][0][wi] = __fmaf_rn(wa0, xvv, facc[dw][0][wi]);
                        facc[dw][1][wi] = __fmaf_rn(wa1, xvv, facc[dw][1][wi]);
                        facc[dw][2][wi] = __fmaf_rn(wa2, xvv, facc[dw][2][wi]);
                        facc[dw][3][wi] = __fmaf_rn(wa3, xvv, facc[dw][3][wi]);
                    }
                }
            }
        }

        // per-shift LSQ psum quantization, then accumulate (exact multiples of ap)
        #pragma unroll
        for (int dw = 0; dw < 3; ++dw)
            #pragma unroll
            for (int oi = 0; oi < 4; ++oi)
                #pragma unroll
                for (int wi = 0; wi < 4; ++wi) {
                    float q = fminf(fmaxf(__fdiv_rn(facc[dw][oi][wi], ap), -4.f), 3.f);
                    out_acc[oi][wi] = __fadd_rn(out_acc[oi][wi], __fmul_rn(rintf(q), ap));
                }
    }

    // epilogue: BN (+residual) + ReLU with jax-matching rounding (NO fma contraction)
    const size_t obase0 = ((size_t)b * OCH) * (HH * WW) + (size_t)h * WW + w0;
    #pragma unroll
    for (int oi = 0; oi < 4; ++oi) {
        int o = o0 + oi;
        float invs = __fdiv_rn(gamma[o], sqrtf(__fadd_rn(var[o], 1e-5f)));
        float sh   = __fadd_rn(beta[o], -__fmul_rn(mean[o], invs));
        size_t base = obase0 + (size_t)o * (HH * WW);
        float vals[4];
        #pragma unroll
        for (int wi = 0; wi < 4; ++wi)
            vals[wi] = __fadd_rn(__fmul_rn(out_acc[oi][wi], invs), sh);
        if (add_res) {
            float4 rr = *(const float4*)(resid + base);
            vals[0] = __fadd_rn(vals[0], rr.x); vals[1] = __fadd_rn(vals[1], rr.y);
            vals[2] = __fadd_rn(vals[2], rr.z); vals[3] = __fadd_rn(vals[3], rr.w);
        }
        float4 s = make_float4(fmaxf(vals[0], 0.f), fmaxf(vals[1], 0.f),
                               fmaxf(vals[2], 0.f), fmaxf(vals[3], 0.f));
        *(float4*)(out + base) = s;
    }
}

extern "C" void kernel_launch(void* const* d_in, const int* in_sizes, int n_in,
                              void* d_out, int out_size) {
    const float* x    = (const float*)d_in[0];
    const float* W1   = (const float*)d_in[1];
    const float* a_w1 = (const float*)d_in[2];
    const float* W2   = (const float*)d_in[3];
    const float* a_w2 = (const float*)d_in[4];
    const float* a_p1 = (const float*)d_in[5];
    const float* a_p2 = (const float*)d_in[6];
    const float* g1   = (const float*)d_in[7];
    const float* b1   = (const float*)d_in[8];
    const float* m1   = (const float*)d_in[9];
    const float* v1   = (const float*)d_in[10];
    const float* g2   = (const float*)d_in[11];
    const float* b2   = (const float*)d_in[12];
    const float* m2   = (const float*)d_in[13];
    const float* v2   = (const float*)d_in[14];
    float* out = (float*)d_out;

    float *t, *w1q, *w2q;
    cudaGetSymbolAddress((void**)&t,   g_t);
    cudaGetSymbolAddress((void**)&w1q, g_w1);
    cudaGetSymbolAddress((void**)&w2q, g_w2);

    const int smem_bytes = (3 * CCH * 58 + 3 * 32 * OCH) * (int)sizeof(float); // 138240
    cudaFuncSetAttribute(conv_kernel, cudaFuncAttributeMaxDynamicSharedMemorySize, smem_bytes);

    const int nw = 9 * CCH * OCH;
    quant_w_kernel<<<(nw + 255) / 256, 256>>>(W1, a_w1, w1q);
    quant_w_kernel<<<(nw + 255) / 256, 256>>>(W2, a_w2, w2q);

    dim3 grid(HH, BB);
    conv_kernel<<<grid, NTHR, smem_bytes>>>(x, w1q, a_p1, g1, b1, m1, v1, nullptr, t, 0);
    conv_kernel<<<grid, NTHR, smem_bytes>>>(t, w2q, a_p2, g2, b2, m2, v2, x, out, 1);
}

// round 11
// speedup vs baseline: 2.5351x; 1.2598x over previous
#include <cuda_runtime.h>
#include <cstdint>

#define CCH 128
#define OCH 128
#define HH  56
#define WW  56
#define BB  32

#define NTHR 448   // 14 warps: og = tid&31 (4 o each), wg = tid>>5 (0..13, 4 w each)

// scratch: intermediate activations + quantized (transposed) weights
__device__ float g_t[(size_t)BB * CCH * HH * WW];     // ~51.4 MB
__device__ float g_w1[9 * CCH * OCH];                  // [i][c][o]
__device__ float g_w2[9 * CCH * OCH];

// Effective LSQ alpha, matching jax grad_scale forward rounding exactly
__device__ __forceinline__ float lsq_alpha_eff(float a, double g) {
    float s32 = (float)g;
    float om  = (float)(1.0 - g);
    return __fadd_rn(__fmul_rn(a, s32), __fmul_rn(a, om));
}

__device__ __forceinline__ void cp_async16(uint32_t saddr, const void* gaddr) {
    asm volatile("cp.async.cg.shared.global [%0], [%1], 16;" :: "r"(saddr), "l"(gaddr));
}
__device__ __forceinline__ void cp_commit() {
    asm volatile("cp.async.commit_group;");
}
__device__ __forceinline__ void cp_wait1() {
    asm volatile("cp.async.wait_group 1;");
}
__device__ __forceinline__ void cp_wait0() {
    asm volatile("cp.async.wait_group 0;");
}
__device__ __forceinline__ uint32_t smem_u32(const void* p) {
    uint32_t a;
    asm("{ .reg .u64 t; cvta.to.shared.u64 t, %1; cvt.u32.u64 %0, t; }" : "=r"(a) : "l"(p));
    return a;
}

// wq_t[i][c][o] = round(clip(W[i][o][c]/a_eff, -4, 3)) * a_eff
__global__ void quant_w_kernel(const float* __restrict__ W,
                               const float* __restrict__ a_w,
                               float* __restrict__ wt) {
    int idx = blockIdx.x * blockDim.x + threadIdx.x;
    if (idx >= 9 * CCH * OCH) return;
    int o = idx % OCH;
    int c = (idx / OCH) % CCH;
    int i = idx / (OCH * CCH);
    const double gw = 1.0 / sqrt((double)(OCH * CCH * 3));   // 1/sqrt(49152)
    float a = lsq_alpha_eff(a_w[i], gw);
    float v = __fdiv_rn(W[((size_t)i * OCH + o) * CCH + c], a);
    v = fminf(fmaxf(v, -4.f), 3.f);
    wt[idx] = __fmul_rn(rintf(v), a);
}

// Issue cp.async for weight stage s = r*4 + ch into buffer buf.
// Copies wqt[(dw*3+r)*CCH + ch*32 + cc][0..127] for dw=0..2, cc=0..31  (3072 float4)
__device__ __forceinline__ void stage_w_async(const float* __restrict__ wqt,
                                              float* buf, int s, int tid) {
    const int r  = s >> 2;
    const int ch = s & 3;
    uint32_t sbase = smem_u32(buf);
    #pragma unroll
    for (int k = 0; k < 7; ++k) {
        int idx = tid + k * NTHR;           // float4 index, 0..3071
        if (idx < 3072) {
            int o4  = idx & 31;             // 32 float4 per row
            int row = idx >> 5;             // dw*32 + cc
            int cc  = row & 31;
            int dw  = row >> 5;
            const float* g = wqt + ((size_t)(dw * 3 + r) * CCH + ch * 32 + cc) * OCH + o4 * 4;
            cp_async16(sbase + (uint32_t)idx * 16u, g);
        }
    }
    cp_commit();
}

// One block = one (b, h) output row: out[b][0..127][h][0..55]
__global__ __launch_bounds__(NTHR, 1)
void conv_kernel(const float* __restrict__ xin,       // [B][C][H][W]
                 const float* __restrict__ wqt,       // [9][C][O], i = dw*3+dh
                 const float* __restrict__ ap_ptr,    // scalar alpha_p
                 const float* __restrict__ gamma, const float* __restrict__ beta,
                 const float* __restrict__ mean,  const float* __restrict__ var,
                 const float* __restrict__ resid,
                 float* __restrict__ out,
                 int add_res) {
    extern __shared__ float smem[];
    float* xs  = smem;                        // [3][128][58]  (87168 B)
    float* wsA = smem + 3 * CCH * 58;         // [3][32][128]  (49152 B)
    float* wsB = wsA + 3 * 32 * OCH;          // [3][32][128]  (49152 B)

    const int h   = blockIdx.x;
    const int b   = blockIdx.y;
    const int tid = threadIdx.x;
    const int og  = tid & 31;
    const int wg  = tid >> 5;            // 0..13
    const int o0  = og * 4;
    const int w0  = wg * 4;

    // stage 3 padded input rows
    for (int idx = tid; idx < 3 * CCH * 58; idx += NTHR) {
        int wi = idx % 58;
        int rc = idx / 58;
        int c  = rc % CCH;
        int r  = rc / CCH;
        int hs = h + r - 1;
        int w  = wi - 1;
        float v = 0.f;
        if ((unsigned)hs < HH && (unsigned)w < WW)
            v = xin[(((size_t)b * CCH + c) * HH + hs) * WW + w];
        xs[idx] = v;
    }

    const double gp = 1.0 / sqrt((double)BB * OCH * HH * WW * 3.0);
    const float ap = lsq_alpha_eff(ap_ptr[0], gp);

    float out_acc[4][4];
    #pragma unroll
    for (int oi = 0; oi < 4; ++oi)
        #pragma unroll
        for (int wi = 0; wi < 4; ++wi) out_acc[oi][wi] = 0.f;

    float facc[3][4][4];

    // prologue: prefetch stage 0
    stage_w_async(wqt, wsA, 0, tid);

    for (int s = 0; s < 12; ++s) {          // s = r*4 + ch
        const int r  = s >> 2;
        const int ch = s & 3;
        float* cur = (s & 1) ? wsB : wsA;
        float* nxt = (s & 1) ? wsA : wsB;

        if (ch == 0) {
            #pragma unroll
            for (int dw = 0; dw < 3; ++dw)
                #pragma unroll
                for (int oi = 0; oi < 4; ++oi)
                    #pragma unroll
                    for (int wi = 0; wi < 4; ++wi) facc[dw][oi][wi] = 0.f;
        }

        // prefetch next stage into the buffer freed at end of stage s-1
        if (s + 1 < 12) { stage_w_async(wqt, nxt, s + 1, tid); cp_wait1(); }
        else            { cp_wait0(); }
        __syncthreads();                    // cur visible to all; xs ready (s=0)

        const float* xbase = xs + (r * CCH + ch * 32) * 58 + w0;
        #pragma unroll 4
        for (int cc = 0; cc < 32; ++cc) {
            const float* xp = xbase + cc * 58;
            float2 xa = *(const float2*)(xp);
            float2 xb = *(const float2*)(xp + 2);
            float2 xc = *(const float2*)(xp + 4);
            float xv[6] = {xa.x, xa.y, xb.x, xb.y, xc.x, xc.y};
            #pragma unroll
            for (int dw = 0; dw < 3; ++dw) {
                float4 w4 = *(const float4*)(cur + (dw * 32 + cc) * OCH + o0);
                float wa0 = w4.x, wa1 = w4.y, wa2 = w4.z, wa3 = w4.w;
                #pragma unroll
                for (int wi = 0; wi < 4; ++wi) {
                    float xvv = xv[wi + dw];
                    facc[dw][0][wi] = __fmaf_rn(wa0, xvv, facc[dw][0][wi]);
                    facc[dw][1][wi] = __fmaf_rn(wa1, xvv, facc[dw][1][wi]);
                    facc[dw][2][wi] = __fmaf_rn(wa2, xvv, facc[dw][2][wi]);
                    facc[dw][3][wi] = __fmaf_rn(wa3, xvv, facc[dw][3][wi]);
                }
            }
        }
        __syncthreads();                    // all done with cur -> refillable at s+1

        if (ch == 3) {
            // per-shift LSQ psum quantization, then accumulate (exact multiples of ap)
            #pragma unroll
            for (int dw = 0; dw < 3; ++dw)
                #pragma unroll
                for (int oi = 0; oi < 4; ++oi)
                    #pragma unroll
                    for (int wi = 0; wi < 4; ++wi) {
                        float q = fminf(fmaxf(__fdiv_rn(facc[dw][oi][wi], ap), -4.f), 3.f);
                        out_acc[oi][wi] = __fadd_rn(out_acc[oi][wi], __fmul_rn(rintf(q), ap));
                    }
        }
    }

    // epilogue: BN (+residual) + ReLU with jax-matching rounding (NO fma contraction)
    const size_t obase0 = ((size_t)b * OCH) * (HH * WW) + (size_t)h * WW + w0;
    #pragma unroll
    for (int oi = 0; oi < 4; ++oi) {
        int o = o0 + oi;
        float invs = __fdiv_rn(gamma[o], sqrtf(__fadd_rn(var[o], 1e-5f)));
        float sh   = __fadd_rn(beta[o], -__fmul_rn(mean[o], invs));
        size_t base = obase0 + (size_t)o * (HH * WW);
        float vals[4];
        #pragma unroll
        for (int wi = 0; wi < 4; ++wi)
            vals[wi] = __fadd_rn(__fmul_rn(out_acc[oi][wi], invs), sh);
        if (add_res) {
            float4 rr = *(const float4*)(resid + base);
            vals[0] = __fadd_rn(vals[0], rr.x); vals[1] = __fadd_rn(vals[1], rr.y);
            vals[2] = __fadd_rn(vals[2], rr.z); vals[3] = __fadd_rn(vals[3], rr.w);
        }
        float4 sv = make_float4(fmaxf(vals[0], 0.f), fmaxf(vals[1], 0.f),
                                fmaxf(vals[2], 0.f), fmaxf(vals[3], 0.f));
        *(float4*)(out + base) = sv;
    }
}

extern "C" void kernel_launch(void* const* d_in, const int* in_sizes, int n_in,
                              void* d_out, int out_size) {
    const float* x    = (const float*)d_in[0];
    const float* W1   = (const float*)d_in[1];
    const float* a_w1 = (const float*)d_in[2];
    const float* W2   = (const float*)d_in[3];
    const float* a_w2 = (const float*)d_in[4];
    const float* a_p1 = (const float*)d_in[5];
    const float* a_p2 = (const float*)d_in[6];
    const float* g1   = (const float*)d_in[7];
    const float* b1   = (const float*)d_in[8];
    const float* m1   = (const float*)d_in[9];
    const float* v1   = (const float*)d_in[10];
    const float* g2   = (const float*)d_in[11];
    const float* b2   = (const float*)d_in[12];
    const float* m2   = (const float*)d_in[13];
    const float* v2   = (const float*)d_in[14];
    float* out = (float*)d_out;

    float *t, *w1q, *w2q;
    cudaGetSymbolAddress((void**)&t,   g_t);
    cudaGetSymbolAddress((void**)&w1q, g_w1);
    cudaGetSymbolAddress((void**)&w2q, g_w2);

    const int smem_bytes = (3 * CCH * 58 + 2 * 3 * 32 * OCH) * (int)sizeof(float); // 185472
    cudaFuncSetAttribute(conv_kernel, cudaFuncAttributeMaxDynamicSharedMemorySize, smem_bytes);

    const int nw = 9 * CCH * OCH;
    quant_w_kernel<<<(nw + 255) / 256, 256>>>(W1, a_w1, w1q);
    quant_w_kernel<<<(nw + 255) / 256, 256>>>(W2, a_w2, w2q);

    dim3 grid(HH, BB);
    conv_kernel<<<grid, NTHR, smem_bytes>>>(x, w1q, a_p1, g1, b1, m1, v1, nullptr, t, 0);
    conv_kernel<<<grid, NTHR, smem_bytes>>>(t, w2q, a_p2, g2, b2, m2, v2, x, out, 1);
}